// round 1
// baseline (speedup 1.0000x reference)
#include <cuda_runtime.h>
#include <cuda_bf16.h>
#include <math.h>

// Problem constants (match reference)
#define NN 100000
#define EE 600000
#define GG 64
#define HH 128
#define STEPS 4

// ---------------- scratch (device globals; allocation-free) ----------------
__device__ __align__(256) float d_h  [(size_t)NN * HH];       // node hidden
__device__ __align__(256) float d_y  [(size_t)NN * 512];      // [m | gh] fused
__device__ __align__(256) float d_agg[(size_t)NN * HH];       // scatter target
__device__ __align__(256) float d_gi [(size_t)NN * 384];      // agg @ Wih^T
__device__ __align__(256) float d_WihT [HH * 384];            // [128,384]
__device__ __align__(256) float d_Wcomb[STEPS * HH * 512];    // per-step [128,512]
__device__ __align__(256) float d_biasc[512];
__device__ __align__(256) float d_pool[2 * GG * HH];
__device__ __align__(256) float d_cnt [2 * GG];

// ---------------- prep: build W_ih^T, [W_s | W_hh^T], combined bias ---------
__global__ void vspn_prep(const float* __restrict__ ggc,   // [4,128,128]
                          const float* __restrict__ wih,   // [384,128]
                          const float* __restrict__ whh,   // [384,128]
                          const float* __restrict__ bhh)   // [384]
{
    int idx = blockIdx.x * blockDim.x + threadIdx.x;
    if (idx < HH * 384) {                       // WihT[k,r] = wih[r,k]
        int k = idx / 384, r = idx % 384;
        d_WihT[idx] = wih[r * HH + k];
    }
    if (idx < STEPS * HH * 512) {
        int s = idx / (HH * 512);
        int rem = idx % (HH * 512);
        int k = rem / 512, c = rem % 512;
        float v;
        if (c < HH) v = ggc[(s * HH + k) * HH + c];
        else        v = whh[(c - HH) * HH + k]; // whh^T
        d_Wcomb[idx] = v;
    }
    if (idx < 512) d_biasc[idx] = (idx < HH) ? 0.f : bhh[idx - HH];
}

// ---------------- SGEMM: C[M,Nc] = A[M,K] @ B[K,Nc] (+bias)(+relu) ----------
#define BM 128
#define BN 128
#define BK 8
#define TM 8
#define TN 8
__global__ __launch_bounds__(256)
void vspn_sgemm(const float* __restrict__ A, const float* __restrict__ B,
                const float* __restrict__ bias, float* __restrict__ C,
                int M, int Nc, int K, int act)
{
    __shared__ float As[BK][BM];
    __shared__ float Bs[BK][BN];
    int tid = threadIdx.x;
    int block_row = blockIdx.y * BM;
    int block_col = blockIdx.x * BN;
    int tr = tid / (BN / TN);   // 0..15
    int tc = tid % (BN / TN);   // 0..15

    float acc[TM][TN];
#pragma unroll
    for (int i = 0; i < TM; i++)
#pragma unroll
        for (int j = 0; j < TN; j++) acc[i][j] = 0.f;

    int aRow = tid >> 1;            // 0..127
    int aCol = (tid & 1) * 4;       // 0 or 4
    int bRow = tid >> 5;            // 0..7
    int bCol = (tid & 31) * 4;      // 0..124

    bool kvec = ((K & 3) == 0);     // A rows 16B-aligned only if K%4==0

    for (int k0 = 0; k0 < K; k0 += BK) {
        // load A tile (BM x BK), store transposed
        {
            int gr = block_row + aRow;
            float v0 = 0.f, v1 = 0.f, v2 = 0.f, v3 = 0.f;
            if (gr < M) {
                const float* ap = A + (size_t)gr * K;
                if (kvec && (k0 + aCol + 3) < K) {
                    float4 v = *reinterpret_cast<const float4*>(ap + k0 + aCol);
                    v0 = v.x; v1 = v.y; v2 = v.z; v3 = v.w;
                } else {
                    int kk = k0 + aCol;
                    if (kk + 0 < K) v0 = ap[kk + 0];
                    if (kk + 1 < K) v1 = ap[kk + 1];
                    if (kk + 2 < K) v2 = ap[kk + 2];
                    if (kk + 3 < K) v3 = ap[kk + 3];
                }
            }
            As[aCol + 0][aRow] = v0;
            As[aCol + 1][aRow] = v1;
            As[aCol + 2][aRow] = v2;
            As[aCol + 3][aRow] = v3;
        }
        // load B tile (BK x BN); Nc is always a multiple of 128 here
        {
            int gk = k0 + bRow;
            float4 v = make_float4(0.f, 0.f, 0.f, 0.f);
            if (gk < K) {
                int gc = block_col + bCol;
                v = *reinterpret_cast<const float4*>(B + (size_t)gk * Nc + gc);
            }
            Bs[bRow][bCol + 0] = v.x;
            Bs[bRow][bCol + 1] = v.y;
            Bs[bRow][bCol + 2] = v.z;
            Bs[bRow][bCol + 3] = v.w;
        }
        __syncthreads();

#pragma unroll
        for (int k = 0; k < BK; k++) {
            float ra[TM], rb[TN];
#pragma unroll
            for (int i = 0; i < TM; i++) ra[i] = As[k][tr * TM + i];
#pragma unroll
            for (int j = 0; j < TN; j++) rb[j] = Bs[k][tc * TN + j];
#pragma unroll
            for (int i = 0; i < TM; i++)
#pragma unroll
                for (int j = 0; j < TN; j++) acc[i][j] += ra[i] * rb[j];
        }
        __syncthreads();
    }

#pragma unroll
    for (int i = 0; i < TM; i++) {
        int row = block_row + tr * TM + i;
        if (row >= M) continue;
#pragma unroll
        for (int j = 0; j < TN; j++) {
            int col = block_col + tc * TN + j;
            float v = acc[i][j];
            if (bias) v += bias[col];
            if (act == 1) v = fmaxf(v, 0.f);
            C[(size_t)row * Nc + col] = v;
        }
    }
}

// ---------------- scatter: agg[dst] += y[src, 0:128] (warp per edge) --------
__global__ void vspn_scatter(const float* __restrict__ y, const int* __restrict__ ei,
                             float* __restrict__ agg, int E)
{
    int gwarp = (blockIdx.x * blockDim.x + threadIdx.x) >> 5;
    int lane  = threadIdx.x & 31;
    if (gwarp >= E) return;
    int src = ei[gwarp];
    int dst = ei[E + gwarp];
    float4 v = reinterpret_cast<const float4*>(y + (size_t)src * 512)[lane];
    float* a = agg + (size_t)dst * HH + lane * 4;
    atomicAdd(a + 0, v.x);
    atomicAdd(a + 1, v.y);
    atomicAdd(a + 2, v.z);
    atomicAdd(a + 3, v.w);
}

// ---------------- GRU fuse: h = GRUCell(gi, gh-from-y, h) -------------------
__global__ void vspn_gru(const float* __restrict__ gi, const float* __restrict__ y,
                         float* __restrict__ h, int total)
{
    int idx = blockIdx.x * blockDim.x + threadIdx.x;
    if (idx >= total) return;
    int n = idx >> 7;
    int j = idx & 127;
    const float* gip = gi + (size_t)n * 384;
    const float* ghp = y + (size_t)n * 512 + HH;  // gh lives in cols 128..511
    float ir = gip[j],        iz = gip[HH + j],  inn = gip[2 * HH + j];
    float hr = ghp[j],        hz = ghp[HH + j],  hn  = ghp[2 * HH + j];
    float hv = h[idx];
    float r = 1.f / (1.f + __expf(-(ir + hr)));
    float z = 1.f / (1.f + __expf(-(iz + hz)));
    float nn = tanhf(inn + r * hn);
    h[idx] = (1.f - z) * nn + z * hv;
}

// ---------------- pool: pool[b] += relu(h[n]), cnt[b] += 1 ------------------
__global__ void vspn_pool(const float* __restrict__ h, const int* __restrict__ batch,
                          float* __restrict__ pool, float* __restrict__ cnt, int Nn)
{
    __shared__ int sb[128];
    int j  = threadIdx.x;          // feature
    int n0 = blockIdx.x * 128;
    int nend = min(n0 + 128, Nn);
    int cn = nend - n0;
    if (n0 + j < Nn) sb[j] = batch[n0 + j];
    __syncthreads();
    float sum = 0.f, rc = 0.f;
    int cur = sb[0];
    for (int t = 0; t < cn; t++) {
        int b = sb[t];
        if (b != cur) {
            atomicAdd(&pool[(size_t)cur * HH + j], sum);
            if (j == 0) atomicAdd(&cnt[cur], rc);
            sum = 0.f; rc = 0.f; cur = b;
        }
        sum += fmaxf(h[(size_t)(n0 + t) * HH + j], 0.f);
        rc += 1.f;
    }
    atomicAdd(&pool[(size_t)cur * HH + j], sum);
    if (j == 0) atomicAdd(&cnt[cur], rc);
}

// ---------------- head: g=[gb|gv]; softplus(relu(g@W1+b1)@W2+b2) ------------
__global__ void vspn_head(const float* __restrict__ W1, const float* __restrict__ b1,
                          const float* __restrict__ W2, const float* __restrict__ b2,
                          float* __restrict__ out)
{
    int g = blockIdx.x;    // graph
    int k = threadIdx.x;   // 0..255
    __shared__ float gsh[256];
    __shared__ float tsh[256];
    float cb = fmaxf(d_cnt[g], 1.f);
    float cv = fmaxf(d_cnt[GG + g], 1.f);
    if (k < HH) gsh[k] = d_pool[(size_t)g * HH + k] / cb;
    else        gsh[k] = d_pool[(size_t)(GG + g) * HH + (k - HH)] / cv;
    __syncthreads();
    float acc = b1[k];
    for (int j = 0; j < 256; j++) acc += gsh[j] * W1[j * 256 + k];
    float t = fmaxf(acc, 0.f);
    tsh[k] = t * W2[k];
    __syncthreads();
    for (int s = 128; s > 0; s >>= 1) {
        if (k < s) tsh[k] += tsh[k + s];
        __syncthreads();
    }
    if (k == 0) {
        float x = tsh[0] + b2[0];
        out[g] = fmaxf(x, 0.f) + log1pf(expf(-fabsf(x)));  // stable softplus
    }
}

// ---------------- launch ----------------------------------------------------
extern "C" void kernel_launch(void* const* d_in, const int* in_sizes, int n_in,
                              void* d_out, int out_size)
{
    const float* x_b   = (const float*)d_in[0];
    const int*   ei_b  = (const int*)  d_in[1];
    const int*   bat_b = (const int*)  d_in[2];
    const float* x_v   = (const float*)d_in[3];
    const int*   ei_v  = (const int*)  d_in[4];
    const int*   bat_v = (const int*)  d_in[5];
    const float* Wemb_b= (const float*)d_in[6];
    const float* Wemb_v= (const float*)d_in[7];
    const float* ggc   = (const float*)d_in[8];
    const float* w_ih  = (const float*)d_in[9];
    const float* w_hh  = (const float*)d_in[10];
    const float* b_ih  = (const float*)d_in[11];
    const float* b_hh  = (const float*)d_in[12];
    const float* W1    = (const float*)d_in[13];
    const float* b1    = (const float*)d_in[14];
    const float* W2    = (const float*)d_in[15];
    const float* b2    = (const float*)d_in[16];
    float* out = (float*)d_out;

    const int FB = in_sizes[0] / NN;   // 90
    const int FV = in_sizes[3] / NN;   // 20

    float *p_h, *p_y, *p_agg, *p_gi, *p_WihT, *p_Wcomb, *p_biasc, *p_pool, *p_cnt;
    cudaGetSymbolAddress((void**)&p_h,     d_h);
    cudaGetSymbolAddress((void**)&p_y,     d_y);
    cudaGetSymbolAddress((void**)&p_agg,   d_agg);
    cudaGetSymbolAddress((void**)&p_gi,    d_gi);
    cudaGetSymbolAddress((void**)&p_WihT,  d_WihT);
    cudaGetSymbolAddress((void**)&p_Wcomb, d_Wcomb);
    cudaGetSymbolAddress((void**)&p_biasc, d_biasc);
    cudaGetSymbolAddress((void**)&p_pool,  d_pool);
    cudaGetSymbolAddress((void**)&p_cnt,   d_cnt);

    // prep combined weights
    vspn_prep<<<(STEPS * HH * 512 + 255) / 256, 256>>>(ggc, w_ih, w_hh, b_hh);
    // zero pooled accumulators
    cudaMemsetAsync(p_pool, 0, sizeof(float) * 2 * GG * HH);
    cudaMemsetAsync(p_cnt,  0, sizeof(float) * 2 * GG);

    const int rowBlocks = (NN + BM - 1) / BM;
    const int gruBlocks = (NN * HH + 255) / 256;
    const int scatBlocks = (EE * 32 + 255) / 256;
    const int poolBlocks = (NN + 127) / 128;

    for (int graph = 0; graph < 2; graph++) {
        const float* x    = graph ? x_v   : x_b;
        const float* Wemb = graph ? Wemb_v: Wemb_b;
        const int*   ei   = graph ? ei_v  : ei_b;
        const int*   bat  = graph ? bat_v : bat_b;
        const int    F    = graph ? FV    : FB;

        // h = relu(x @ Wemb)
        {
            dim3 grid(1, rowBlocks);
            vspn_sgemm<<<grid, 256>>>(x, Wemb, nullptr, p_h, NN, HH, F, 1);
        }
        for (int s = 0; s < STEPS; s++) {
            // y[:, :128] = h@W_s ; y[:, 128:] = h@W_hh^T + b_hh
            {
                dim3 grid(512 / BN, rowBlocks);
                vspn_sgemm<<<grid, 256>>>(p_h, p_Wcomb + (size_t)s * HH * 512,
                                          p_biasc, p_y, NN, 512, HH, 0);
            }
            cudaMemsetAsync(p_agg, 0, sizeof(float) * (size_t)NN * HH);
            vspn_scatter<<<scatBlocks, 256>>>(p_y, ei, p_agg, EE);
            // gi = agg @ Wih^T + b_ih
            {
                dim3 grid(384 / BN, rowBlocks);
                vspn_sgemm<<<grid, 256>>>(p_agg, p_WihT, b_ih, p_gi, NN, 384, HH, 0);
            }
            vspn_gru<<<gruBlocks, 256>>>(p_gi, p_y, p_h, NN * HH);
        }
        // mean-pool relu(h)
        vspn_pool<<<poolBlocks, 128>>>(p_h, bat,
                                       p_pool + (size_t)graph * GG * HH,
                                       p_cnt + graph * GG, NN);
    }

    vspn_head<<<GG, 256>>>(W1, b1, W2, b2, out);
}

// round 3
// speedup vs baseline: 2.6210x; 2.6210x over previous
#include <cuda_runtime.h>
#include <cuda_bf16.h>
#include <cstdint>
#include <math.h>

#define NN 100000
#define EE 600000
#define GG 64
#define HH 128
#define STEPS 4

#define MODE_Y   0
#define MODE_GI  1
#define MODE_EMB 2

// ---------------- scratch (device globals; allocation-free) ----------------
__device__ __align__(256) float          d_h  [(size_t)NN * HH];   // node hidden fp32
__device__ __align__(256) __nv_bfloat16  d_y  [(size_t)NN * 512];  // [m | gh] bf16
__device__ __align__(256) float          d_agg[(size_t)NN * HH];   // scatter target fp32
__device__ __align__(256) float          d_gi [(size_t)NN * 384];  // gi fp32
// Pre-swizzled bf16 weight tiles: 21 tiles x 64KB ([hi 32KB | lo 32KB])
//   0..15 : y GEMM (s*4+nt), 16..18 : gi GEMM, 19 : emb bond, 20 : emb voro
__device__ __align__(256) char  d_img[21 * 65536];
__device__ __align__(256) float d_pool[2 * GG * HH];
__device__ __align__(256) float d_cnt [2 * GG];

// ---------------- helpers ---------------------------------------------------
__device__ __forceinline__ uint32_t smem_u32(const void* p) {
    uint32_t a;
    asm("{ .reg .u64 t; cvta.to.shared.u64 t, %1; cvt.u32.u64 %0, t; }" : "=r"(a) : "l"(p));
    return a;
}
// byte offset inside a 128x128 bf16 tile, xor-swizzled per 16B chunk
__host__ __device__ __forceinline__ uint32_t swz(int row, int k) {
    return (uint32_t)(row * 256 + ((((k >> 3) ^ (row & 7)) << 4) | ((k & 7) << 1)));
}

#define LDSM4(R0, R1, R2, R3, ADDR) \
    asm volatile("ldmatrix.sync.aligned.m8n8.x4.shared.b16 {%0,%1,%2,%3}, [%4];" \
                 : "=r"(R0), "=r"(R1), "=r"(R2), "=r"(R3) : "r"(ADDR))

#define MMA16816(D, A0, A1, A2, A3, B0, B1) \
    asm volatile("mma.sync.aligned.m16n8k16.row.col.f32.bf16.bf16.f32 " \
                 "{%0,%1,%2,%3}, {%4,%5,%6,%7}, {%8,%9}, {%0,%1,%2,%3};" \
                 : "+f"((D)[0]), "+f"((D)[1]), "+f"((D)[2]), "+f"((D)[3]) \
                 : "r"(A0), "r"(A1), "r"(A2), "r"(A3), "r"(B0), "r"(B1))

// ---------------- prep: bf16 hi/lo pre-swizzled weight tiles ----------------
__global__ void vspn_prep(const float* __restrict__ ggc,   // [4,128,128]
                          const float* __restrict__ wih,   // [384,128]
                          const float* __restrict__ whh,   // [384,128]
                          const float* __restrict__ wembB, // [FB,128]
                          const float* __restrict__ wembV, // [FV,128]
                          int FB, int FV)
{
    int idx = blockIdx.x * blockDim.x + threadIdx.x;
    if (idx >= 21 * 16384) return;
    int t = idx / 16384;
    int e = idx % 16384;
    int n = e >> 7;     // output col within tile (0..127)
    int k = e & 127;    // K index
    float v = 0.f;
    if (t < 16) {
        int s = t >> 2, nt = t & 3;
        int c = nt * 128 + n;
        v = (c < 128) ? ggc[(s * 128 + k) * 128 + c]
                      : whh[(size_t)(c - 128) * 128 + k];
    } else if (t < 19) {
        int c = (t - 16) * 128 + n;
        v = wih[(size_t)c * 128 + k];
    } else if (t == 19) {
        v = (k < FB) ? wembB[(size_t)k * 128 + n] : 0.f;
    } else {
        v = (k < FV) ? wembV[(size_t)k * 128 + n] : 0.f;
    }
    __nv_bfloat16 hi = __float2bfloat16_rn(v);
    __nv_bfloat16 lo = __float2bfloat16_rn(v - __bfloat162float(hi));
    uint32_t off = swz(n, k);
    *(__nv_bfloat16*)(d_img + (size_t)t * 65536 + off)         = hi;
    *(__nv_bfloat16*)(d_img + (size_t)t * 65536 + 32768 + off) = lo;
}

// ---------------- HMMA GEMM: C[M,128*NT] = A[M,K<=128] @ B(hi+lo) -----------
// mode Y  : yout bf16          (NT=4)
// mode GI : gi fp32            (NT=3)
// mode EMB: hio = relu (fp32)  (NT=1)
#define SM_TOTAL 98304   // As 32KB | Bhi 32KB | Blo 32KB

__global__ void __launch_bounds__(256, 1)
vspn_mma(const float* __restrict__ A, int Kin,
         const char* __restrict__ Bimg, int NT, int mode,
         float* __restrict__ fout,            // GI / EMB target
         __nv_bfloat16* __restrict__ yout,    // Y target
         int M)
{
    extern __shared__ char smem[];
    const int tid  = threadIdx.x;
    const int wid  = tid >> 5;
    const int lane = tid & 31;
    const int wr   = wid & 3;       // row-block 0..3 (32 rows each)
    const int wc   = wid >> 2;      // col-block 0..1 (64 cols each)

    // ---- stage A: fp32 -> bf16, swizzled (one half-row per thread) ----
    {
        int r = tid >> 1;
        int half = tid & 1;
        int node = blockIdx.x * 128 + r;
        bool valid = node < M;
        const float* ap = A + (size_t)node * Kin;
#pragma unroll
        for (int i = 0; i < 8; i++) {
            int k0 = half * 64 + i * 8;
            float v[8];
            if (Kin == 128) {
                float4 f0 = valid ? *reinterpret_cast<const float4*>(ap + k0)
                                  : make_float4(0.f, 0.f, 0.f, 0.f);
                float4 f1 = valid ? *reinterpret_cast<const float4*>(ap + k0 + 4)
                                  : make_float4(0.f, 0.f, 0.f, 0.f);
                v[0] = f0.x; v[1] = f0.y; v[2] = f0.z; v[3] = f0.w;
                v[4] = f1.x; v[5] = f1.y; v[6] = f1.z; v[7] = f1.w;
            } else {
#pragma unroll
                for (int q = 0; q < 8; q++) {
                    int k = k0 + q;
                    v[q] = (valid && k < Kin) ? ap[k] : 0.f;
                }
            }
            uint32_t p[4];
#pragma unroll
            for (int q = 0; q < 4; q++) {
                __nv_bfloat162 b2 = __floats2bfloat162_rn(v[2 * q], v[2 * q + 1]);
                p[q] = *reinterpret_cast<uint32_t*>(&b2);
            }
            *reinterpret_cast<uint4*>(smem + swz(r, k0)) = make_uint4(p[0], p[1], p[2], p[3]);
        }
    }

    const uint32_t sA  = smem_u32(smem);
    const uint32_t sBh = sA + 32768;
    const uint32_t sBl = sA + 65536;

    // per-thread ldmatrix row/k lane offsets
    const int arow = wr * 32 + (lane & 15);
    const int akl  = (lane >> 4) << 3;
    const int brow = wc * 64 + ((lane >> 4) << 3) + (lane & 7);
    const int bkl  = ((lane >> 3) & 1) << 3;

    for (int nt = 0; nt < NT; nt++) {
        __syncthreads();   // A staged / previous compute finished
        // ---- stage B tile (hi+lo = 64KB) ----
        {
            const uint4* src = reinterpret_cast<const uint4*>(Bimg + (size_t)nt * 65536);
            uint4* dst = reinterpret_cast<uint4*>(smem + 32768);
#pragma unroll
            for (int i = 0; i < 16; i++) dst[tid + i * 256] = src[tid + i * 256];
        }
        __syncthreads();

        float acc[2][8][4];
#pragma unroll
        for (int i = 0; i < 2; i++)
#pragma unroll
            for (int j = 0; j < 8; j++)
#pragma unroll
                for (int q = 0; q < 4; q++) acc[i][j][q] = 0.f;

#pragma unroll
        for (int ks = 0; ks < 8; ks++) {
            const int kk = ks * 16;
            uint32_t a0[4], a1[4];
            LDSM4(a0[0], a0[1], a0[2], a0[3], sA + swz(arow,      kk + akl));
            LDSM4(a1[0], a1[1], a1[2], a1[3], sA + swz(arow + 16, kk + akl));
#pragma unroll
            for (int nb = 0; nb < 4; nb++) {
                uint32_t bh[4], bl[4];
                LDSM4(bh[0], bh[1], bh[2], bh[3], sBh + swz(brow + nb * 16, kk + bkl));
                LDSM4(bl[0], bl[1], bl[2], bl[3], sBl + swz(brow + nb * 16, kk + bkl));
                int j0 = nb * 2;
                MMA16816(acc[0][j0],     a0[0], a0[1], a0[2], a0[3], bh[0], bh[1]);
                MMA16816(acc[1][j0],     a1[0], a1[1], a1[2], a1[3], bh[0], bh[1]);
                MMA16816(acc[0][j0 + 1], a0[0], a0[1], a0[2], a0[3], bh[2], bh[3]);
                MMA16816(acc[1][j0 + 1], a1[0], a1[1], a1[2], a1[3], bh[2], bh[3]);
                MMA16816(acc[0][j0],     a0[0], a0[1], a0[2], a0[3], bl[0], bl[1]);
                MMA16816(acc[1][j0],     a1[0], a1[1], a1[2], a1[3], bl[0], bl[1]);
                MMA16816(acc[0][j0 + 1], a0[0], a0[1], a0[2], a0[3], bl[2], bl[3]);
                MMA16816(acc[1][j0 + 1], a1[0], a1[1], a1[2], a1[3], bl[2], bl[3]);
            }
        }

        // ---- epilogue ----
        const int gnode0 = blockIdx.x * 128 + wr * 32 + (lane >> 2);
        const int cbase  = wc * 64 + (lane & 3) * 2;

        if (mode == MODE_Y) {
#pragma unroll
            for (int i = 0; i < 2; i++)
#pragma unroll
                for (int rr = 0; rr < 2; rr++) {
                    int node = gnode0 + i * 16 + rr * 8;
                    if (node >= M) continue;
                    __nv_bfloat16* yp = yout + (size_t)node * 512 + nt * 128 + cbase;
#pragma unroll
                    for (int j = 0; j < 8; j++) {
                        __nv_bfloat162 b2 = __floats2bfloat162_rn(acc[i][j][rr * 2],
                                                                  acc[i][j][rr * 2 + 1]);
                        *reinterpret_cast<uint32_t*>(yp + j * 8) =
                            *reinterpret_cast<uint32_t*>(&b2);
                    }
                }
        } else if (mode == MODE_GI) {
#pragma unroll
            for (int i = 0; i < 2; i++)
#pragma unroll
                for (int rr = 0; rr < 2; rr++) {
                    int node = gnode0 + i * 16 + rr * 8;
                    if (node >= M) continue;
                    float* gp = fout + (size_t)node * 384 + nt * 128 + cbase;
#pragma unroll
                    for (int j = 0; j < 8; j++)
                        *reinterpret_cast<float2*>(gp + j * 8) =
                            make_float2(acc[i][j][rr * 2], acc[i][j][rr * 2 + 1]);
                }
        } else { // MODE_EMB
#pragma unroll
            for (int i = 0; i < 2; i++)
#pragma unroll
                for (int rr = 0; rr < 2; rr++) {
                    int node = gnode0 + i * 16 + rr * 8;
                    if (node >= M) continue;
                    float* hp = fout + (size_t)node * 128 + cbase;
#pragma unroll
                    for (int j = 0; j < 8; j++)
                        *reinterpret_cast<float2*>(hp + j * 8) =
                            make_float2(fmaxf(acc[i][j][rr * 2], 0.f),
                                        fmaxf(acc[i][j][rr * 2 + 1], 0.f));
                }
        }
    }
}

// ---------------- scatter: agg[dst] += m[src] (bf16 gather, red.v4) ---------
__global__ void vspn_scatter(const __nv_bfloat16* __restrict__ y,
                             const int* __restrict__ ei,
                             float* __restrict__ agg, int E)
{
    int gw   = (blockIdx.x * blockDim.x + threadIdx.x) >> 5;
    int lane = threadIdx.x & 31;
    if (gw >= E) return;
    int src = ei[gw];
    int dst = ei[E + gw];
    uint2 v = *reinterpret_cast<const uint2*>(y + (size_t)src * 512 + lane * 4);
    float2 a = __bfloat1622float2(*reinterpret_cast<__nv_bfloat162*>(&v.x));
    float2 b = __bfloat1622float2(*reinterpret_cast<__nv_bfloat162*>(&v.y));
    float* pa = agg + (size_t)dst * HH + lane * 4;
    asm volatile("red.global.add.v4.f32 [%0], {%1, %2, %3, %4};"
                 :: "l"(pa), "f"(a.x), "f"(a.y), "f"(b.x), "f"(b.y) : "memory");
}

// ---------------- GRU elementwise: h = GRUCell(gi+bih, gh+bhh, h) -----------
__global__ void vspn_gru(const float* __restrict__ gi,
                         const __nv_bfloat16* __restrict__ y,
                         float* __restrict__ h,
                         const float* __restrict__ bih,
                         const float* __restrict__ bhh)
{
    int idx = blockIdx.x * blockDim.x + threadIdx.x;
    if (idx >= NN * 32) return;
    int n  = idx >> 5;
    int j4 = (idx & 31) * 4;

    const float* gp = gi + (size_t)n * 384 + j4;
    float4 ir4 = *reinterpret_cast<const float4*>(gp);
    float4 iz4 = *reinterpret_cast<const float4*>(gp + 128);
    float4 in4 = *reinterpret_cast<const float4*>(gp + 256);

    const __nv_bfloat16* yp = y + (size_t)n * 512 + 128 + j4;
    uint2 hr2 = *reinterpret_cast<const uint2*>(yp);
    uint2 hz2 = *reinterpret_cast<const uint2*>(yp + 128);
    uint2 hn2 = *reinterpret_cast<const uint2*>(yp + 256);

    float4 br = *reinterpret_cast<const float4*>(bih + j4);
    float4 bz = *reinterpret_cast<const float4*>(bih + 128 + j4);
    float4 bn = *reinterpret_cast<const float4*>(bih + 256 + j4);
    float4 cr = *reinterpret_cast<const float4*>(bhh + j4);
    float4 cz = *reinterpret_cast<const float4*>(bhh + 128 + j4);
    float4 cn = *reinterpret_cast<const float4*>(bhh + 256 + j4);

    float4 h4 = *reinterpret_cast<float4*>(h + (size_t)n * 128 + j4);

    float ir[4] = {ir4.x + br.x, ir4.y + br.y, ir4.z + br.z, ir4.w + br.w};
    float iz[4] = {iz4.x + bz.x, iz4.y + bz.y, iz4.z + bz.z, iz4.w + bz.w};
    float in_[4]= {in4.x + bn.x, in4.y + bn.y, in4.z + bn.z, in4.w + bn.w};

    float hr[4], hz[4], hn[4];
    {
        float2 f;
        f = __bfloat1622float2(*reinterpret_cast<__nv_bfloat162*>(&hr2.x)); hr[0]=f.x; hr[1]=f.y;
        f = __bfloat1622float2(*reinterpret_cast<__nv_bfloat162*>(&hr2.y)); hr[2]=f.x; hr[3]=f.y;
        f = __bfloat1622float2(*reinterpret_cast<__nv_bfloat162*>(&hz2.x)); hz[0]=f.x; hz[1]=f.y;
        f = __bfloat1622float2(*reinterpret_cast<__nv_bfloat162*>(&hz2.y)); hz[2]=f.x; hz[3]=f.y;
        f = __bfloat1622float2(*reinterpret_cast<__nv_bfloat162*>(&hn2.x)); hn[0]=f.x; hn[1]=f.y;
        f = __bfloat1622float2(*reinterpret_cast<__nv_bfloat162*>(&hn2.y)); hn[2]=f.x; hn[3]=f.y;
    }
    float crr[4] = {cr.x, cr.y, cr.z, cr.w};
    float czz[4] = {cz.x, cz.y, cz.z, cz.w};
    float cnn[4] = {cn.x, cn.y, cn.z, cn.w};
    float hv[4]  = {h4.x, h4.y, h4.z, h4.w};
    float ho[4];
#pragma unroll
    for (int q = 0; q < 4; q++) {
        float r = 1.f / (1.f + __expf(-(ir[q] + hr[q] + crr[q])));
        float z = 1.f / (1.f + __expf(-(iz[q] + hz[q] + czz[q])));
        float nng = tanhf(in_[q] + r * (hn[q] + cnn[q]));
        ho[q] = (1.f - z) * nng + z * hv[q];
    }
    *reinterpret_cast<float4*>(h + (size_t)n * 128 + j4) =
        make_float4(ho[0], ho[1], ho[2], ho[3]);
}

// ---------------- pool: pool[b] += relu(h[n]), cnt[b] += 1 ------------------
__global__ void vspn_pool(const float* __restrict__ h, const int* __restrict__ batch,
                          float* __restrict__ pool, float* __restrict__ cnt, int Nn)
{
    __shared__ int sbh[128];
    int j  = threadIdx.x;
    int n0 = blockIdx.x * 128;
    int nend = min(n0 + 128, Nn);
    int cn = nend - n0;
    if (n0 + j < Nn) sbh[j] = batch[n0 + j];
    __syncthreads();
    float sum = 0.f, rc = 0.f;
    int cur = sbh[0];
    for (int t = 0; t < cn; t++) {
        int b = sbh[t];
        if (b != cur) {
            atomicAdd(&pool[(size_t)cur * HH + j], sum);
            if (j == 0) atomicAdd(&cnt[cur], rc);
            sum = 0.f; rc = 0.f; cur = b;
        }
        sum += fmaxf(h[(size_t)(n0 + t) * HH + j], 0.f);
        rc += 1.f;
    }
    atomicAdd(&pool[(size_t)cur * HH + j], sum);
    if (j == 0) atomicAdd(&cnt[cur], rc);
}

// ---------------- head ------------------------------------------------------
__global__ void vspn_head(const float* __restrict__ W1, const float* __restrict__ b1,
                          const float* __restrict__ W2, const float* __restrict__ b2,
                          float* __restrict__ out)
{
    int g = blockIdx.x;
    int k = threadIdx.x;
    __shared__ float gsh[256];
    __shared__ float tsh[256];
    float cb = fmaxf(d_cnt[g], 1.f);
    float cv = fmaxf(d_cnt[GG + g], 1.f);
    if (k < HH) gsh[k] = d_pool[(size_t)g * HH + k] / cb;
    else        gsh[k] = d_pool[(size_t)(GG + g) * HH + (k - HH)] / cv;
    __syncthreads();
    float acc = b1[k];
    for (int j = 0; j < 256; j++) acc += gsh[j] * W1[j * 256 + k];
    float t = fmaxf(acc, 0.f);
    tsh[k] = t * W2[k];
    __syncthreads();
    for (int s = 128; s > 0; s >>= 1) {
        if (k < s) tsh[k] += tsh[k + s];
        __syncthreads();
    }
    if (k == 0) {
        float x = tsh[0] + b2[0];
        out[g] = fmaxf(x, 0.f) + log1pf(expf(-fabsf(x)));
    }
}

// ---------------- launch ----------------------------------------------------
extern "C" void kernel_launch(void* const* d_in, const int* in_sizes, int n_in,
                              void* d_out, int out_size)
{
    const float* x_b   = (const float*)d_in[0];
    const int*   ei_b  = (const int*)  d_in[1];
    const int*   bat_b = (const int*)  d_in[2];
    const float* x_v   = (const float*)d_in[3];
    const int*   ei_v  = (const int*)  d_in[4];
    const int*   bat_v = (const int*)  d_in[5];
    const float* Wemb_b= (const float*)d_in[6];
    const float* Wemb_v= (const float*)d_in[7];
    const float* ggc   = (const float*)d_in[8];
    const float* w_ih  = (const float*)d_in[9];
    const float* w_hh  = (const float*)d_in[10];
    const float* b_ih  = (const float*)d_in[11];
    const float* b_hh  = (const float*)d_in[12];
    const float* W1    = (const float*)d_in[13];
    const float* b1    = (const float*)d_in[14];
    const float* W2    = (const float*)d_in[15];
    const float* b2    = (const float*)d_in[16];
    float* out = (float*)d_out;

    const int FB = in_sizes[0] / NN;
    const int FV = in_sizes[3] / NN;

    float *p_h, *p_agg, *p_gi, *p_pool, *p_cnt;
    __nv_bfloat16* p_y;
    char* p_img;
    cudaGetSymbolAddress((void**)&p_h,    d_h);
    cudaGetSymbolAddress((void**)&p_y,    d_y);
    cudaGetSymbolAddress((void**)&p_agg,  d_agg);
    cudaGetSymbolAddress((void**)&p_gi,   d_gi);
    cudaGetSymbolAddress((void**)&p_img,  d_img);
    cudaGetSymbolAddress((void**)&p_pool, d_pool);
    cudaGetSymbolAddress((void**)&p_cnt,  d_cnt);

    cudaFuncSetAttribute(vspn_mma, cudaFuncAttributeMaxDynamicSharedMemorySize, SM_TOTAL);

    vspn_prep<<<(21 * 16384 + 255) / 256, 256>>>(ggc, w_ih, w_hh, Wemb_b, Wemb_v, FB, FV);
    cudaMemsetAsync(p_pool, 0, sizeof(float) * 2 * GG * HH);
    cudaMemsetAsync(p_cnt,  0, sizeof(float) * 2 * GG);

    const int MT = (NN + 127) / 128;          // 782
    const int scatBlocks = (EE * 32 + 255) / 256;
    const int gruBlocks  = (NN * 32 + 255) / 256;
    const int poolBlocks = (NN + 127) / 128;

    for (int graph = 0; graph < 2; graph++) {
        const float* x   = graph ? x_v   : x_b;
        const int*   ei  = graph ? ei_v  : ei_b;
        const int*   bat = graph ? bat_v : bat_b;
        const int    F   = graph ? FV    : FB;
        const char*  eimg = p_img + (size_t)(19 + graph) * 65536;

        // h = relu(x @ Wemb)
        vspn_mma<<<MT, 256, SM_TOTAL>>>(x, F, eimg, 1, MODE_EMB, p_h, nullptr, NN);
        for (int s = 0; s < STEPS; s++) {
            // y = bf16([h@W_s | h@Whh^T])
            vspn_mma<<<MT, 256, SM_TOTAL>>>(p_h, 128, p_img + (size_t)s * 4 * 65536, 4,
                                            MODE_Y, nullptr, p_y, NN);
            cudaMemsetAsync(p_agg, 0, sizeof(float) * (size_t)NN * HH);
            vspn_scatter<<<scatBlocks, 256>>>(p_y, ei, p_agg, EE);
            // gi = agg @ Wih^T
            vspn_mma<<<MT, 256, SM_TOTAL>>>(p_agg, 128, p_img + (size_t)16 * 65536, 3,
                                            MODE_GI, p_gi, nullptr, NN);
            vspn_gru<<<gruBlocks, 256>>>(p_gi, p_y, p_h, b_ih, b_hh);
        }
        vspn_pool<<<poolBlocks, 128>>>(p_h, bat,
                                       p_pool + (size_t)graph * GG * HH,
                                       p_cnt + graph * GG, NN);
    }

    vspn_head<<<GG, 256>>>(W1, b1, W2, b2, out);
}

// round 4
// speedup vs baseline: 3.3216x; 1.2673x over previous
#include <cuda_runtime.h>
#include <cuda_bf16.h>
#include <cstdint>
#include <math.h>

#define NN 100000
#define EE 600000
#define GG 64
#define HH 128
#define STEPS 4
#define NB_SCAN 196   // ceil(NN/512)

// ---------------- scratch (device globals; allocation-free) ----------------
__device__ __align__(256) float          d_h  [(size_t)NN * HH];   // node hidden fp32
__device__ __align__(256) __nv_bfloat16  d_ym [(size_t)NN * HH];   // messages m bf16
__device__ __align__(256) float          d_agg[(size_t)NN * HH];   // gathered messages
// Pre-swizzled bf16 weight tiles, 64KB each ([hi 32KB | lo 32KB]):
//  t0..3 : W_s (m GEMM) ; t4..6 : Whh gates r,z,n ; t7..9 : Wih gates ; t10,11 : emb
__device__ __align__(256) char  d_img[12 * 65536];
__device__ __align__(256) float d_pool[2 * GG * HH];
__device__ __align__(256) float d_cnt [2 * GG];
// CSR scratch
__device__ int d_ecnt[NN];
__device__ int d_ecur[NN];
__device__ int d_eoff[NN + 1];
__device__ int d_eidx[EE];
__device__ int d_bsum[256];
__device__ int d_boff[256];

// ---------------- helpers ---------------------------------------------------
__device__ __forceinline__ uint32_t smem_u32(const void* p) {
    uint32_t a;
    asm("{ .reg .u64 t; cvta.to.shared.u64 t, %1; cvt.u32.u64 %0, t; }" : "=r"(a) : "l"(p));
    return a;
}
__host__ __device__ __forceinline__ uint32_t swz(int row, int k) {
    return (uint32_t)(row * 256 + ((((k >> 3) ^ (row & 7)) << 4) | ((k & 7) << 1)));
}
__device__ __forceinline__ float sigm(float x) { return 1.f / (1.f + __expf(-x)); }

#define LDSM4(R0, R1, R2, R3, ADDR) \
    asm volatile("ldmatrix.sync.aligned.m8n8.x4.shared.b16 {%0,%1,%2,%3}, [%4];" \
                 : "=r"(R0), "=r"(R1), "=r"(R2), "=r"(R3) : "r"(ADDR))

#define MMA16816(D, A0, A1, A2, A3, B0, B1) \
    asm volatile("mma.sync.aligned.m16n8k16.row.col.f32.bf16.bf16.f32 " \
                 "{%0,%1,%2,%3}, {%4,%5,%6,%7}, {%8,%9}, {%0,%1,%2,%3};" \
                 : "+f"((D)[0]), "+f"((D)[1]), "+f"((D)[2]), "+f"((D)[3]) \
                 : "r"(A0), "r"(A1), "r"(A2), "r"(A3), "r"(B0), "r"(B1))

// full 128x128x128 hi+lo MMA pass accumulating into acc
__device__ __forceinline__ void mma_pass(uint32_t sA, uint32_t sB,
                                         int arow, int akl, int brow, int bkl,
                                         float (&acc)[2][8][4])
{
#pragma unroll
    for (int ks = 0; ks < 8; ks++) {
        const int kk = ks * 16;
        uint32_t a0[4], a1[4];
        LDSM4(a0[0], a0[1], a0[2], a0[3], sA + swz(arow,      kk + akl));
        LDSM4(a1[0], a1[1], a1[2], a1[3], sA + swz(arow + 16, kk + akl));
#pragma unroll
        for (int nb = 0; nb < 4; nb++) {
            uint32_t bh[4], bl[4];
            LDSM4(bh[0], bh[1], bh[2], bh[3], sB + swz(brow + nb * 16, kk + bkl));
            LDSM4(bl[0], bl[1], bl[2], bl[3], sB + 32768 + swz(brow + nb * 16, kk + bkl));
            int j0 = nb * 2;
            MMA16816(acc[0][j0],     a0[0], a0[1], a0[2], a0[3], bh[0], bh[1]);
            MMA16816(acc[1][j0],     a1[0], a1[1], a1[2], a1[3], bh[0], bh[1]);
            MMA16816(acc[0][j0 + 1], a0[0], a0[1], a0[2], a0[3], bh[2], bh[3]);
            MMA16816(acc[1][j0 + 1], a1[0], a1[1], a1[2], a1[3], bh[2], bh[3]);
            MMA16816(acc[0][j0],     a0[0], a0[1], a0[2], a0[3], bl[0], bl[1]);
            MMA16816(acc[1][j0],     a1[0], a1[1], a1[2], a1[3], bl[0], bl[1]);
            MMA16816(acc[0][j0 + 1], a0[0], a0[1], a0[2], a0[3], bl[2], bl[3]);
            MMA16816(acc[1][j0 + 1], a1[0], a1[1], a1[2], a1[3], bl[2], bl[3]);
        }
    }
}

__device__ __forceinline__ void zero_acc(float (&acc)[2][8][4]) {
#pragma unroll
    for (int i = 0; i < 2; i++)
#pragma unroll
        for (int j = 0; j < 8; j++)
#pragma unroll
            for (int q = 0; q < 4; q++) acc[i][j][q] = 0.f;
}

// stage fp32 A[128 rows, Kin<=128] -> bf16 swizzled smem tile
__device__ __forceinline__ void stage_A(const float* __restrict__ A, int Kin, int M,
                                        int node0, char* dst, int tid)
{
    int r = tid >> 1;
    int half = tid & 1;
    int node = node0 + r;
    bool valid = node < M;
    const float* ap = A + (size_t)node * Kin;
#pragma unroll
    for (int i = 0; i < 8; i++) {
        int k0 = half * 64 + i * 8;
        float v[8];
        if (Kin == 128) {
            float4 f0 = valid ? *reinterpret_cast<const float4*>(ap + k0)
                              : make_float4(0.f, 0.f, 0.f, 0.f);
            float4 f1 = valid ? *reinterpret_cast<const float4*>(ap + k0 + 4)
                              : make_float4(0.f, 0.f, 0.f, 0.f);
            v[0] = f0.x; v[1] = f0.y; v[2] = f0.z; v[3] = f0.w;
            v[4] = f1.x; v[5] = f1.y; v[6] = f1.z; v[7] = f1.w;
        } else {
#pragma unroll
            for (int q = 0; q < 8; q++) {
                int k = k0 + q;
                v[q] = (valid && k < Kin) ? ap[k] : 0.f;
            }
        }
        uint32_t p[4];
#pragma unroll
        for (int q = 0; q < 4; q++) {
            __nv_bfloat162 b2 = __floats2bfloat162_rn(v[2 * q], v[2 * q + 1]);
            p[q] = *reinterpret_cast<uint32_t*>(&b2);
        }
        *reinterpret_cast<uint4*>(dst + swz(r, k0)) = make_uint4(p[0], p[1], p[2], p[3]);
    }
}

__device__ __forceinline__ void load_B(char* dst, const char* __restrict__ src, int tid) {
    const uint4* s = reinterpret_cast<const uint4*>(src);
    uint4* d = reinterpret_cast<uint4*>(dst);
#pragma unroll
    for (int i = 0; i < 16; i++) d[tid + i * 256] = s[tid + i * 256];
}

// ---------------- prep: bf16 hi/lo pre-swizzled weight tiles ----------------
__global__ void vspn_prep(const float* __restrict__ ggc,   // [4,128,128]
                          const float* __restrict__ wih,   // [384,128]
                          const float* __restrict__ whh,   // [384,128]
                          const float* __restrict__ wembB, // [FB,128]
                          const float* __restrict__ wembV, // [FV,128]
                          int FB, int FV)
{
    int idx = blockIdx.x * blockDim.x + threadIdx.x;
    if (idx >= 12 * 16384) return;
    int t = idx / 16384;
    int e = idx % 16384;
    int n = e >> 7;
    int k = e & 127;
    float v = 0.f;
    if (t < 4) {
        v = ggc[(t * 128 + k) * 128 + n];
    } else if (t < 7) {
        int g = t - 4;
        v = whh[(size_t)(g * 128 + n) * 128 + k];
    } else if (t < 10) {
        int g = t - 7;
        v = wih[(size_t)(g * 128 + n) * 128 + k];
    } else if (t == 10) {
        v = (k < FB) ? wembB[(size_t)k * 128 + n] : 0.f;
    } else {
        v = (k < FV) ? wembV[(size_t)k * 128 + n] : 0.f;
    }
    __nv_bfloat16 hi = __float2bfloat16_rn(v);
    __nv_bfloat16 lo = __float2bfloat16_rn(v - __bfloat162float(hi));
    uint32_t off = swz(n, k);
    *(__nv_bfloat16*)(d_img + (size_t)t * 65536 + off)         = hi;
    *(__nv_bfloat16*)(d_img + (size_t)t * 65536 + 32768 + off) = lo;
}

// ---------------- CSR build -------------------------------------------------
__global__ void k_hist(const int* __restrict__ ei) {
    int e = blockIdx.x * blockDim.x + threadIdx.x;
    if (e < EE) atomicAdd(&d_ecnt[ei[EE + e]], 1);
}
__global__ void k_blocksum() {
    __shared__ int sh[512];
    int i = blockIdx.x * 512 + threadIdx.x;
    sh[threadIdx.x] = (i < NN) ? d_ecnt[i] : 0;
    __syncthreads();
    for (int s = 256; s > 0; s >>= 1) {
        if (threadIdx.x < s) sh[threadIdx.x] += sh[threadIdx.x + s];
        __syncthreads();
    }
    if (threadIdx.x == 0) d_bsum[blockIdx.x] = sh[0];
}
__global__ void k_scanbsum() {
    __shared__ int sh[256];
    int t = threadIdx.x;
    int v = (t < NB_SCAN) ? d_bsum[t] : 0;
    sh[t] = v;
    __syncthreads();
    for (int off = 1; off < 256; off <<= 1) {
        int x = (t >= off) ? sh[t - off] : 0;
        __syncthreads();
        sh[t] += x;
        __syncthreads();
    }
    if (t < NB_SCAN) d_boff[t] = sh[t] - v;   // exclusive
}
__global__ void k_scanfinal() {
    __shared__ int sh[512];
    int t = threadIdx.x;
    int i = blockIdx.x * 512 + t;
    int v = (i < NN) ? d_ecnt[i] : 0;
    sh[t] = v;
    __syncthreads();
    for (int off = 1; off < 512; off <<= 1) {
        int x = (t >= off) ? sh[t - off] : 0;
        __syncthreads();
        sh[t] += x;
        __syncthreads();
    }
    if (i < NN) {
        int excl = d_boff[blockIdx.x] + sh[t] - v;
        d_eoff[i] = excl;
        d_ecur[i] = excl;
        if (i == NN - 1) d_eoff[NN] = excl + v;
    }
}
__global__ void k_fill(const int* __restrict__ ei) {
    int e = blockIdx.x * blockDim.x + threadIdx.x;
    if (e >= EE) return;
    int p = atomicAdd(&d_ecur[ei[EE + e]], 1);
    d_eidx[p] = ei[e];
}

// ---------------- gather: agg[d] = sum_{e in CSR(d)} m[src_e] ---------------
__global__ void vspn_gather(const __nv_bfloat16* __restrict__ ym,
                            float* __restrict__ agg)
{
    int w = (blockIdx.x * blockDim.x + threadIdx.x) >> 5;
    if (w >= NN) return;
    int lane = threadIdx.x & 31;
    int e0 = d_eoff[w], e1 = d_eoff[w + 1];
    float4 s = make_float4(0.f, 0.f, 0.f, 0.f);
    for (int e = e0; e < e1; e++) {
        int src = d_eidx[e];
        uint2 v = *reinterpret_cast<const uint2*>(ym + (size_t)src * 128 + lane * 4);
        float2 a = __bfloat1622float2(*reinterpret_cast<__nv_bfloat162*>(&v.x));
        float2 b = __bfloat1622float2(*reinterpret_cast<__nv_bfloat162*>(&v.y));
        s.x += a.x; s.y += a.y; s.z += b.x; s.w += b.y;
    }
    *reinterpret_cast<float4*>(agg + (size_t)w * 128 + lane * 4) = s;
}

// ---------------- embed: h = relu(x@Wemb); ym = bf16(h@W0) ------------------
#define SM_EMB 98304
__global__ void __launch_bounds__(256, 1)
vspn_emb(const float* __restrict__ x, int Kin,
         const char* __restrict__ imgE, const char* __restrict__ imgM,
         float* __restrict__ h, __nv_bfloat16* __restrict__ ym, int M)
{
    extern __shared__ char smem[];
    const int tid = threadIdx.x, lane = tid & 31, wid = tid >> 5;
    const int wr = wid & 3, wc = wid >> 2;
    const int arow = wr * 32 + (lane & 15), akl = (lane >> 4) << 3;
    const int brow = wc * 64 + ((lane >> 4) << 3) + (lane & 7), bkl = ((lane >> 3) & 1) << 3;
    const int rl0 = wr * 32 + (lane >> 2);
    const int cb  = wc * 64 + (lane & 3) * 2;
    const int node0 = blockIdx.x * 128;

    stage_A(x, Kin, M, node0, smem, tid);
    uint32_t sA = smem_u32(smem), sB = sA + 32768;
    __syncthreads();
    load_B(smem + 32768, imgE, tid);
    __syncthreads();

    float acc[2][8][4];
    zero_acc(acc);
    mma_pass(sA, sB, arow, akl, brow, bkl, acc);
    __syncthreads();   // A & B consumed

    // h = relu(acc): write gmem + stage bf16 into A slot
#pragma unroll
    for (int i = 0; i < 2; i++)
#pragma unroll
        for (int rr = 0; rr < 2; rr++) {
            int rl = rl0 + i * 16 + rr * 8;
            int node = node0 + rl;
            bool valid = node < M;
#pragma unroll
            for (int j = 0; j < 8; j++) {
                int c = cb + j * 8;
                float v0 = fmaxf(acc[i][j][rr * 2], 0.f);
                float v1 = fmaxf(acc[i][j][rr * 2 + 1], 0.f);
                if (valid)
                    *reinterpret_cast<float2*>(h + (size_t)node * 128 + c) = make_float2(v0, v1);
                __nv_bfloat162 b2 = __floats2bfloat162_rn(v0, v1);
                *reinterpret_cast<uint32_t*>(smem + swz(rl, c)) = *reinterpret_cast<uint32_t*>(&b2);
            }
        }
    __syncthreads();
    load_B(smem + 32768, imgM, tid);
    __syncthreads();
    zero_acc(acc);
    mma_pass(sA, sB, arow, akl, brow, bkl, acc);
#pragma unroll
    for (int i = 0; i < 2; i++)
#pragma unroll
        for (int rr = 0; rr < 2; rr++) {
            int node = node0 + rl0 + i * 16 + rr * 8;
            if (node >= M) continue;
#pragma unroll
            for (int j = 0; j < 8; j++) {
                int c = cb + j * 8;
                __nv_bfloat162 b2 = __floats2bfloat162_rn(acc[i][j][rr * 2], acc[i][j][rr * 2 + 1]);
                *reinterpret_cast<uint32_t*>(ym + (size_t)node * 128 + c) =
                    *reinterpret_cast<uint32_t*>(&b2);
            }
        }
}

// ---------------- fused step: GRU(h, agg) -> h ; ym = bf16(h@W_next) --------
#define SM_STEP 131072   // A_agg 32K | A_h 32K | B 64K
__global__ void __launch_bounds__(256, 1)
vspn_step(const float* __restrict__ agg, float* __restrict__ h,
          const char* __restrict__ img, int mstep,
          const float* __restrict__ bih, const float* __restrict__ bhh,
          __nv_bfloat16* __restrict__ ym, int M)
{
    extern __shared__ char smem[];
    const int tid = threadIdx.x, lane = tid & 31, wid = tid >> 5;
    const int wr = wid & 3, wc = wid >> 2;
    const int arow = wr * 32 + (lane & 15), akl = (lane >> 4) << 3;
    const int brow = wc * 64 + ((lane >> 4) << 3) + (lane & 7), bkl = ((lane >> 3) & 1) << 3;
    const int rl0 = wr * 32 + (lane >> 2);
    const int cb  = wc * 64 + (lane & 3) * 2;
    const int node0 = blockIdx.x * 128;

    stage_A(agg, 128, M, node0, smem, tid);
    stage_A(h,   128, M, node0, smem + 32768, tid);
    uint32_t sA = smem_u32(smem), sAh = sA + 32768, sB = sA + 65536;

    float acc[2][8][4], rg[2][8][4], ng[2][8][4];

    // ---- gate r (g=0) ----
    __syncthreads();
    load_B(smem + 65536, img + 4 * 65536, tid);    // Whh_r
    __syncthreads();
    zero_acc(acc);
    mma_pass(sAh, sB, arow, akl, brow, bkl, acc);
    __syncthreads();
    load_B(smem + 65536, img + 7 * 65536, tid);    // Wih_r
    __syncthreads();
    mma_pass(sA, sB, arow, akl, brow, bkl, acc);
#pragma unroll
    for (int i = 0; i < 2; i++)
#pragma unroll
        for (int j = 0; j < 8; j++) {
            int c = cb + j * 8;
            float2 b1 = *reinterpret_cast<const float2*>(bih + c);
            float2 b2 = *reinterpret_cast<const float2*>(bhh + c);
#pragma unroll
            for (int rr = 0; rr < 2; rr++) {
                rg[i][j][rr * 2]     = sigm(acc[i][j][rr * 2]     + b1.x + b2.x);
                rg[i][j][rr * 2 + 1] = sigm(acc[i][j][rr * 2 + 1] + b1.y + b2.y);
            }
        }

    // ---- gate n (g=2): tanh(gi_n + b_ih_n + r*(gh_n + b_hh_n)) ----
    __syncthreads();
    load_B(smem + 65536, img + 6 * 65536, tid);    // Whh_n
    __syncthreads();
    zero_acc(acc);
    mma_pass(sAh, sB, arow, akl, brow, bkl, acc);
#pragma unroll
    for (int i = 0; i < 2; i++)
#pragma unroll
        for (int j = 0; j < 8; j++) {
            int c = cb + j * 8;
            float2 b1 = *reinterpret_cast<const float2*>(bih + 256 + c);
            float2 b2 = *reinterpret_cast<const float2*>(bhh + 256 + c);
#pragma unroll
            for (int rr = 0; rr < 2; rr++) {
                acc[i][j][rr * 2]     = rg[i][j][rr * 2]     * (acc[i][j][rr * 2]     + b2.x) + b1.x;
                acc[i][j][rr * 2 + 1] = rg[i][j][rr * 2 + 1] * (acc[i][j][rr * 2 + 1] + b2.y) + b1.y;
            }
        }
    __syncthreads();
    load_B(smem + 65536, img + 9 * 65536, tid);    // Wih_n
    __syncthreads();
    mma_pass(sA, sB, arow, akl, brow, bkl, acc);
#pragma unroll
    for (int i = 0; i < 2; i++)
#pragma unroll
        for (int j = 0; j < 8; j++)
#pragma unroll
            for (int q = 0; q < 4; q++) ng[i][j][q] = tanhf(acc[i][j][q]);

    // ---- gate z (g=1) + combine ----
    __syncthreads();
    load_B(smem + 65536, img + 5 * 65536, tid);    // Whh_z
    __syncthreads();
    zero_acc(acc);
    mma_pass(sAh, sB, arow, akl, brow, bkl, acc);
    __syncthreads();
    load_B(smem + 65536, img + 8 * 65536, tid);    // Wih_z
    __syncthreads();
    mma_pass(sA, sB, arow, akl, brow, bkl, acc);
    __syncthreads();   // all warps done with A slots; safe to restage h_new into sA
#pragma unroll
    for (int i = 0; i < 2; i++)
#pragma unroll
        for (int rr = 0; rr < 2; rr++) {
            int rl = rl0 + i * 16 + rr * 8;
            int node = node0 + rl;
            bool valid = node < M;
#pragma unroll
            for (int j = 0; j < 8; j++) {
                int c = cb + j * 8;
                float2 b1 = *reinterpret_cast<const float2*>(bih + 128 + c);
                float2 b2 = *reinterpret_cast<const float2*>(bhh + 128 + c);
                float z0 = sigm(acc[i][j][rr * 2]     + b1.x + b2.x);
                float z1 = sigm(acc[i][j][rr * 2 + 1] + b1.y + b2.y);
                float2 hp = valid ? *reinterpret_cast<const float2*>(h + (size_t)node * 128 + c)
                                  : make_float2(0.f, 0.f);
                float h0 = (1.f - z0) * ng[i][j][rr * 2]     + z0 * hp.x;
                float h1 = (1.f - z1) * ng[i][j][rr * 2 + 1] + z1 * hp.y;
                if (valid)
                    *reinterpret_cast<float2*>(h + (size_t)node * 128 + c) = make_float2(h0, h1);
                __nv_bfloat162 bb = __floats2bfloat162_rn(h0, h1);
                *reinterpret_cast<uint32_t*>(smem + swz(rl, c)) = *reinterpret_cast<uint32_t*>(&bb);
            }
        }

    // ---- next-step messages: ym = bf16(h_new @ W[mstep]) ----
    if (mstep >= 0) {
        __syncthreads();
        load_B(smem + 65536, img + (size_t)mstep * 65536, tid);
        __syncthreads();
        zero_acc(acc);
        mma_pass(sA, sB, arow, akl, brow, bkl, acc);
#pragma unroll
        for (int i = 0; i < 2; i++)
#pragma unroll
            for (int rr = 0; rr < 2; rr++) {
                int node = node0 + rl0 + i * 16 + rr * 8;
                if (node >= M) continue;
#pragma unroll
                for (int j = 0; j < 8; j++) {
                    int c = cb + j * 8;
                    __nv_bfloat162 b2 = __floats2bfloat162_rn(acc[i][j][rr * 2],
                                                              acc[i][j][rr * 2 + 1]);
                    *reinterpret_cast<uint32_t*>(ym + (size_t)node * 128 + c) =
                        *reinterpret_cast<uint32_t*>(&b2);
                }
            }
    }
}

// ---------------- pool: pool[b] += relu(h[n]), cnt[b] += 1 ------------------
__global__ void vspn_pool(const float* __restrict__ h, const int* __restrict__ batch,
                          float* __restrict__ pool, float* __restrict__ cnt, int Nn)
{
    __shared__ int sbh[128];
    int j  = threadIdx.x;
    int n0 = blockIdx.x * 128;
    int nend = min(n0 + 128, Nn);
    int cn = nend - n0;
    if (n0 + j < Nn) sbh[j] = batch[n0 + j];
    __syncthreads();
    float sum = 0.f, rc = 0.f;
    int cur = sbh[0];
    for (int t = 0; t < cn; t++) {
        int b = sbh[t];
        if (b != cur) {
            atomicAdd(&pool[(size_t)cur * HH + j], sum);
            if (j == 0) atomicAdd(&cnt[cur], rc);
            sum = 0.f; rc = 0.f; cur = b;
        }
        sum += fmaxf(h[(size_t)(n0 + t) * HH + j], 0.f);
        rc += 1.f;
    }
    atomicAdd(&pool[(size_t)cur * HH + j], sum);
    if (j == 0) atomicAdd(&cnt[cur], rc);
}

// ---------------- head ------------------------------------------------------
__global__ void vspn_head(const float* __restrict__ W1, const float* __restrict__ b1,
                          const float* __restrict__ W2, const float* __restrict__ b2,
                          float* __restrict__ out)
{
    int g = blockIdx.x;
    int k = threadIdx.x;
    __shared__ float gsh[256];
    __shared__ float tsh[256];
    float cb = fmaxf(d_cnt[g], 1.f);
    float cv = fmaxf(d_cnt[GG + g], 1.f);
    if (k < HH) gsh[k] = d_pool[(size_t)g * HH + k] / cb;
    else        gsh[k] = d_pool[(size_t)(GG + g) * HH + (k - HH)] / cv;
    __syncthreads();
    float acc = b1[k];
    for (int j = 0; j < 256; j++) acc += gsh[j] * W1[j * 256 + k];
    float t = fmaxf(acc, 0.f);
    tsh[k] = t * W2[k];
    __syncthreads();
    for (int s = 128; s > 0; s >>= 1) {
        if (k < s) tsh[k] += tsh[k + s];
        __syncthreads();
    }
    if (k == 0) {
        float x = tsh[0] + b2[0];
        out[g] = fmaxf(x, 0.f) + log1pf(expf(-fabsf(x)));
    }
}

// ---------------- launch ----------------------------------------------------
extern "C" void kernel_launch(void* const* d_in, const int* in_sizes, int n_in,
                              void* d_out, int out_size)
{
    const float* x_b   = (const float*)d_in[0];
    const int*   ei_b  = (const int*)  d_in[1];
    const int*   bat_b = (const int*)  d_in[2];
    const float* x_v   = (const float*)d_in[3];
    const int*   ei_v  = (const int*)  d_in[4];
    const int*   bat_v = (const int*)  d_in[5];
    const float* Wemb_b= (const float*)d_in[6];
    const float* Wemb_v= (const float*)d_in[7];
    const float* ggc   = (const float*)d_in[8];
    const float* w_ih  = (const float*)d_in[9];
    const float* w_hh  = (const float*)d_in[10];
    const float* b_ih  = (const float*)d_in[11];
    const float* b_hh  = (const float*)d_in[12];
    const float* W1    = (const float*)d_in[13];
    const float* b1    = (const float*)d_in[14];
    const float* W2    = (const float*)d_in[15];
    const float* b2    = (const float*)d_in[16];
    float* out = (float*)d_out;

    const int FB = in_sizes[0] / NN;
    const int FV = in_sizes[3] / NN;

    float *p_h, *p_agg, *p_pool, *p_cnt;
    __nv_bfloat16* p_ym;
    char* p_img;
    int* p_ecnt;
    cudaGetSymbolAddress((void**)&p_h,    d_h);
    cudaGetSymbolAddress((void**)&p_ym,   d_ym);
    cudaGetSymbolAddress((void**)&p_agg,  d_agg);
    cudaGetSymbolAddress((void**)&p_img,  d_img);
    cudaGetSymbolAddress((void**)&p_pool, d_pool);
    cudaGetSymbolAddress((void**)&p_cnt,  d_cnt);
    cudaGetSymbolAddress((void**)&p_ecnt, d_ecnt);

    cudaFuncSetAttribute(vspn_emb,  cudaFuncAttributeMaxDynamicSharedMemorySize, SM_EMB);
    cudaFuncSetAttribute(vspn_step, cudaFuncAttributeMaxDynamicSharedMemorySize, SM_STEP);

    vspn_prep<<<(12 * 16384 + 255) / 256, 256>>>(ggc, w_ih, w_hh, Wemb_b, Wemb_v, FB, FV);
    cudaMemsetAsync(p_pool, 0, sizeof(float) * 2 * GG * HH);
    cudaMemsetAsync(p_cnt,  0, sizeof(float) * 2 * GG);

    const int MT = (NN + 127) / 128;                 // 782
    const int EB = (EE + 255) / 256;                 // 2344
    const int GB = (NN + 7) / 8;                     // 12500 (gather, 8 warps/blk)
    const int poolBlocks = (NN + 127) / 128;

    for (int graph = 0; graph < 2; graph++) {
        const float* x   = graph ? x_v   : x_b;
        const int*   ei  = graph ? ei_v  : ei_b;
        const int*   bat = graph ? bat_v : bat_b;
        const int    F   = graph ? FV    : FB;

        // ---- CSR build for this graph ----
        cudaMemsetAsync(p_ecnt, 0, sizeof(int) * NN);
        k_hist<<<EB, 256>>>(ei);
        k_blocksum<<<NB_SCAN, 512>>>();
        k_scanbsum<<<1, 256>>>();
        k_scanfinal<<<NB_SCAN, 512>>>();
        k_fill<<<EB, 256>>>(ei);

        // ---- embed + m0 ----
        vspn_emb<<<MT, 256, SM_EMB>>>(x, F, p_img + (size_t)(10 + graph) * 65536,
                                      p_img, p_h, p_ym, NN);
        // ---- steps ----
        for (int s = 0; s < STEPS; s++) {
            vspn_gather<<<GB, 256>>>(p_ym, p_agg);
            int mstep = (s < STEPS - 1) ? (s + 1) : -1;
            vspn_step<<<MT, 256, SM_STEP>>>(p_agg, p_h, p_img, mstep,
                                            b_ih, b_hh, p_ym, NN);
        }
        vspn_pool<<<poolBlocks, 128>>>(p_h, bat,
                                       p_pool + (size_t)graph * GG * HH,
                                       p_cnt + graph * GG, NN);
    }

    vspn_head<<<GG, 256>>>(W1, b1, W2, b2, out);
}

// round 5
// speedup vs baseline: 4.2302x; 1.2736x over previous
#include <cuda_runtime.h>
#include <cuda_fp16.h>
#include <cstdint>
#include <math.h>

#define NN 100000
#define EE 600000
#define GG 64
#define HH 128
#define STEPS 4
#define NB_SCAN 196   // ceil(NN/512)
#define TILE 32768    // fp16 128x128 tile bytes

// ---------------- scratch (device globals; allocation-free) ----------------
__device__ __align__(256) float  d_h  [(size_t)NN * HH];   // node hidden fp32
__device__ __align__(256) __half d_ym [(size_t)NN * HH];   // messages m fp16
__device__ __align__(256) float  d_agg[(size_t)NN * HH];   // gathered messages
// Pre-swizzled fp16 weight tiles, 32KB each:
//  t0..3 : W_s ; t4..6 : Whh r,z,n ; t7..9 : Wih r,z,n ; t10,11 : emb
__device__ __align__(256) char  d_img[12 * TILE];
__device__ __align__(256) float d_pool[2 * GG * HH];
__device__ __align__(256) float d_cnt [2 * GG];
// CSR scratch
__device__ int d_ecnt[NN];
__device__ int d_ecur[NN];
__device__ int d_eoff[NN + 1];
__device__ int d_eidx[EE];
__device__ int d_bsum[256];
__device__ int d_boff[256];

// ---------------- helpers ---------------------------------------------------
__device__ __forceinline__ uint32_t smem_u32(const void* p) {
    uint32_t a;
    asm("{ .reg .u64 t; cvta.to.shared.u64 t, %1; cvt.u32.u64 %0, t; }" : "=r"(a) : "l"(p));
    return a;
}
__host__ __device__ __forceinline__ uint32_t swz(int row, int k) {
    return (uint32_t)(row * 256 + ((((k >> 3) ^ (row & 7)) << 4) | ((k & 7) << 1)));
}
__device__ __forceinline__ float sigm(float x) { return 1.f / (1.f + __expf(-x)); }

#define LDSM4(R0, R1, R2, R3, ADDR) \
    asm volatile("ldmatrix.sync.aligned.m8n8.x4.shared.b16 {%0,%1,%2,%3}, [%4];" \
                 : "=r"(R0), "=r"(R1), "=r"(R2), "=r"(R3) : "r"(ADDR))

#define MMA16816(D, A0, A1, A2, A3, B0, B1) \
    asm volatile("mma.sync.aligned.m16n8k16.row.col.f32.f16.f16.f32 " \
                 "{%0,%1,%2,%3}, {%4,%5,%6,%7}, {%8,%9}, {%0,%1,%2,%3};" \
                 : "+f"((D)[0]), "+f"((D)[1]), "+f"((D)[2]), "+f"((D)[3]) \
                 : "r"(A0), "r"(A1), "r"(A2), "r"(A3), "r"(B0), "r"(B1))

// cp.async a 32KB tile (all 256 threads participate), one commit group
__device__ __forceinline__ void cp_tile(uint32_t dst, const char* __restrict__ src, int tid) {
#pragma unroll
    for (int i = 0; i < 8; i++) {
        uint32_t d = dst + tid * 16 + i * 4096;
        const char* s = src + tid * 16 + i * 4096;
        asm volatile("cp.async.cg.shared.global [%0], [%1], 16;" :: "r"(d), "l"(s));
    }
    asm volatile("cp.async.commit_group;");
}
#define CP_WAIT(n) asm volatile("cp.async.wait_group %0;" :: "n"(n))

// one 128x128x128 fp16 MMA pass accumulating into acc
__device__ __forceinline__ void mma_pass(uint32_t sA, uint32_t sB,
                                         int arow, int akl, int brow, int bkl,
                                         float (&acc)[2][8][4])
{
#pragma unroll
    for (int ks = 0; ks < 8; ks++) {
        const int kk = ks * 16;
        uint32_t a0[4], a1[4];
        LDSM4(a0[0], a0[1], a0[2], a0[3], sA + swz(arow,      kk + akl));
        LDSM4(a1[0], a1[1], a1[2], a1[3], sA + swz(arow + 16, kk + akl));
#pragma unroll
        for (int nb = 0; nb < 4; nb++) {
            uint32_t bh[4];
            LDSM4(bh[0], bh[1], bh[2], bh[3], sB + swz(brow + nb * 16, kk + bkl));
            int j0 = nb * 2;
            MMA16816(acc[0][j0],     a0[0], a0[1], a0[2], a0[3], bh[0], bh[1]);
            MMA16816(acc[1][j0],     a1[0], a1[1], a1[2], a1[3], bh[0], bh[1]);
            MMA16816(acc[0][j0 + 1], a0[0], a0[1], a0[2], a0[3], bh[2], bh[3]);
            MMA16816(acc[1][j0 + 1], a1[0], a1[1], a1[2], a1[3], bh[2], bh[3]);
        }
    }
}

__device__ __forceinline__ void zero_acc(float (&acc)[2][8][4]) {
#pragma unroll
    for (int i = 0; i < 2; i++)
#pragma unroll
        for (int j = 0; j < 8; j++)
#pragma unroll
            for (int q = 0; q < 4; q++) acc[i][j][q] = 0.f;
}

// stage fp32 A[128 rows, Kin<=128] -> fp16 swizzled smem tile
__device__ __forceinline__ void stage_A(const float* __restrict__ A, int Kin, int M,
                                        int node0, char* dst, int tid)
{
    int r = tid >> 1;
    int hf = tid & 1;
    int node = node0 + r;
    bool valid = node < M;
    const float* ap = A + (size_t)node * Kin;
#pragma unroll
    for (int i = 0; i < 8; i++) {
        int k0 = hf * 64 + i * 8;
        float v[8];
        if (Kin == 128) {
            float4 f0 = valid ? *reinterpret_cast<const float4*>(ap + k0)
                              : make_float4(0.f, 0.f, 0.f, 0.f);
            float4 f1 = valid ? *reinterpret_cast<const float4*>(ap + k0 + 4)
                              : make_float4(0.f, 0.f, 0.f, 0.f);
            v[0] = f0.x; v[1] = f0.y; v[2] = f0.z; v[3] = f0.w;
            v[4] = f1.x; v[5] = f1.y; v[6] = f1.z; v[7] = f1.w;
        } else {
#pragma unroll
            for (int q = 0; q < 8; q++) {
                int k = k0 + q;
                v[q] = (valid && k < Kin) ? ap[k] : 0.f;
            }
        }
        uint32_t p[4];
#pragma unroll
        for (int q = 0; q < 4; q++) {
            __half2 h2 = __floats2half2_rn(v[2 * q], v[2 * q + 1]);
            p[q] = *reinterpret_cast<uint32_t*>(&h2);
        }
        *reinterpret_cast<uint4*>(dst + swz(r, k0)) = make_uint4(p[0], p[1], p[2], p[3]);
    }
}

// ---------------- prep: fp16 pre-swizzled weight tiles ----------------------
__global__ void vspn_prep(const float* __restrict__ ggc,   // [4,128,128]
                          const float* __restrict__ wih,   // [384,128]
                          const float* __restrict__ whh,   // [384,128]
                          const float* __restrict__ wembB, // [FB,128]
                          const float* __restrict__ wembV, // [FV,128]
                          int FB, int FV)
{
    int idx = blockIdx.x * blockDim.x + threadIdx.x;
    if (idx >= 12 * 16384) return;
    int t = idx / 16384;
    int e = idx % 16384;
    int n = e >> 7;
    int k = e & 127;
    float v = 0.f;
    if (t < 4) {
        v = ggc[(t * 128 + k) * 128 + n];
    } else if (t < 7) {
        int g = t - 4;
        v = whh[(size_t)(g * 128 + n) * 128 + k];
    } else if (t < 10) {
        int g = t - 7;
        v = wih[(size_t)(g * 128 + n) * 128 + k];
    } else if (t == 10) {
        v = (k < FB) ? wembB[(size_t)k * 128 + n] : 0.f;
    } else {
        v = (k < FV) ? wembV[(size_t)k * 128 + n] : 0.f;
    }
    *(__half*)(d_img + (size_t)t * TILE + swz(n, k)) = __float2half_rn(v);
}

// ---------------- CSR build -------------------------------------------------
__global__ void k_hist(const int* __restrict__ ei) {
    int e = blockIdx.x * blockDim.x + threadIdx.x;
    if (e < EE) atomicAdd(&d_ecnt[ei[EE + e]], 1);
}
__global__ void k_blocksum() {
    __shared__ int sh[512];
    int i = blockIdx.x * 512 + threadIdx.x;
    sh[threadIdx.x] = (i < NN) ? d_ecnt[i] : 0;
    __syncthreads();
    for (int s = 256; s > 0; s >>= 1) {
        if (threadIdx.x < s) sh[threadIdx.x] += sh[threadIdx.x + s];
        __syncthreads();
    }
    if (threadIdx.x == 0) d_bsum[blockIdx.x] = sh[0];
}
__global__ void k_scanbsum() {
    __shared__ int sh[256];
    int t = threadIdx.x;
    int v = (t < NB_SCAN) ? d_bsum[t] : 0;
    sh[t] = v;
    __syncthreads();
    for (int off = 1; off < 256; off <<= 1) {
        int x = (t >= off) ? sh[t - off] : 0;
        __syncthreads();
        sh[t] += x;
        __syncthreads();
    }
    if (t < NB_SCAN) d_boff[t] = sh[t] - v;   // exclusive
}
__global__ void k_scanfinal() {
    __shared__ int sh[512];
    int t = threadIdx.x;
    int i = blockIdx.x * 512 + t;
    int v = (i < NN) ? d_ecnt[i] : 0;
    sh[t] = v;
    __syncthreads();
    for (int off = 1; off < 512; off <<= 1) {
        int x = (t >= off) ? sh[t - off] : 0;
        __syncthreads();
        sh[t] += x;
        __syncthreads();
    }
    if (i < NN) {
        int excl = d_boff[blockIdx.x] + sh[t] - v;
        d_eoff[i] = excl;
        d_ecur[i] = excl;
        if (i == NN - 1) d_eoff[NN] = excl + v;
    }
}
__global__ void k_fill(const int* __restrict__ ei) {
    int e = blockIdx.x * blockDim.x + threadIdx.x;
    if (e >= EE) return;
    int p = atomicAdd(&d_ecur[ei[EE + e]], 1);
    d_eidx[p] = ei[e];
}

// ---------------- gather: agg[d] = sum_{e in CSR(d)} m[src_e] ---------------
__global__ void vspn_gather(const __half* __restrict__ ym,
                            float* __restrict__ agg)
{
    int w = (blockIdx.x * blockDim.x + threadIdx.x) >> 5;
    if (w >= NN) return;
    int lane = threadIdx.x & 31;
    int e0 = d_eoff[w], e1 = d_eoff[w + 1];
    float4 s = make_float4(0.f, 0.f, 0.f, 0.f);
    for (int e = e0; e < e1; e++) {
        int src = d_eidx[e];
        uint2 v = *reinterpret_cast<const uint2*>(ym + (size_t)src * 128 + lane * 4);
        float2 a = __half22float2(*reinterpret_cast<__half2*>(&v.x));
        float2 b = __half22float2(*reinterpret_cast<__half2*>(&v.y));
        s.x += a.x; s.y += a.y; s.z += b.x; s.w += b.y;
    }
    *reinterpret_cast<float4*>(agg + (size_t)w * 128 + lane * 4) = s;
}

// ---------------- embed: h = relu(x@Wemb); ym = fp16(h@W0) ------------------
#define SM_EMB (3 * TILE)
__global__ void __launch_bounds__(256, 1)
vspn_emb(const float* __restrict__ x, int Kin,
         const char* __restrict__ imgE, const char* __restrict__ imgM,
         float* __restrict__ h, __half* __restrict__ ym, int M)
{
    extern __shared__ char smem[];
    const int tid = threadIdx.x, lane = tid & 31, wid = tid >> 5;
    const int wr = wid & 3, wc = wid >> 2;
    const int arow = wr * 32 + (lane & 15), akl = (lane >> 4) << 3;
    const int brow = wc * 64 + ((lane >> 4) << 3) + (lane & 7), bkl = ((lane >> 3) & 1) << 3;
    const int rl0 = wr * 32 + (lane >> 2);
    const int cb  = wc * 64 + (lane & 3) * 2;
    const int node0 = blockIdx.x * 128;

    uint32_t sA = smem_u32(smem), sB0 = sA + TILE, sB1 = sA + 2 * TILE;
    cp_tile(sB0, imgE, tid);
    cp_tile(sB1, imgM, tid);
    stage_A(x, Kin, M, node0, smem, tid);
    CP_WAIT(1);
    __syncthreads();

    float acc[2][8][4];
    zero_acc(acc);
    mma_pass(sA, sB0, arow, akl, brow, bkl, acc);
    __syncthreads();   // A consumed

    // h = relu(acc): write gmem + restage fp16 into A slot
#pragma unroll
    for (int i = 0; i < 2; i++)
#pragma unroll
        for (int rr = 0; rr < 2; rr++) {
            int rl = rl0 + i * 16 + rr * 8;
            int node = node0 + rl;
            bool valid = node < M;
#pragma unroll
            for (int j = 0; j < 8; j++) {
                int c = cb + j * 8;
                float v0 = fmaxf(acc[i][j][rr * 2], 0.f);
                float v1 = fmaxf(acc[i][j][rr * 2 + 1], 0.f);
                if (valid)
                    *reinterpret_cast<float2*>(h + (size_t)node * 128 + c) = make_float2(v0, v1);
                __half2 h2 = __floats2half2_rn(v0, v1);
                *reinterpret_cast<uint32_t*>(smem + swz(rl, c)) = *reinterpret_cast<uint32_t*>(&h2);
            }
        }
    __syncthreads();
    CP_WAIT(0);
    zero_acc(acc);
    mma_pass(sA, sB1, arow, akl, brow, bkl, acc);
#pragma unroll
    for (int i = 0; i < 2; i++)
#pragma unroll
        for (int rr = 0; rr < 2; rr++) {
            int node = node0 + rl0 + i * 16 + rr * 8;
            if (node >= M) continue;
#pragma unroll
            for (int j = 0; j < 8; j++) {
                int c = cb + j * 8;
                __half2 h2 = __floats2half2_rn(acc[i][j][rr * 2], acc[i][j][rr * 2 + 1]);
                *reinterpret_cast<uint32_t*>(ym + (size_t)node * 128 + c) =
                    *reinterpret_cast<uint32_t*>(&h2);
            }
        }
}

// ---------------- fused step: GRU(h, agg) -> h ; ym = fp16(h@W_next) --------
// B-tile phase order: t4(hh_r) t7(ih_r) t6(hh_n) t9(ih_n) t5(hh_z) t8(ih_z) [tm]
#define SM_STEP (4 * TILE)   // A_agg | A_h | B0 | B1
__global__ void __launch_bounds__(256, 1)
vspn_step(const float* __restrict__ agg, float* __restrict__ h,
          const char* __restrict__ img, int mstep,
          const float* __restrict__ bih, const float* __restrict__ bhh,
          __half* __restrict__ ym, int M)
{
    extern __shared__ char smem[];
    const int tid = threadIdx.x, lane = tid & 31, wid = tid >> 5;
    const int wr = wid & 3, wc = wid >> 2;
    const int arow = wr * 32 + (lane & 15), akl = (lane >> 4) << 3;
    const int brow = wc * 64 + ((lane >> 4) << 3) + (lane & 7), bkl = ((lane >> 3) & 1) << 3;
    const int rl0 = wr * 32 + (lane >> 2);
    const int cb  = wc * 64 + (lane & 3) * 2;
    const int node0 = blockIdx.x * 128;

    uint32_t sA  = smem_u32(smem);
    uint32_t sAh = sA + TILE;
    uint32_t sB0 = sA + 2 * TILE;
    uint32_t sB1 = sA + 3 * TILE;

    cp_tile(sB0, img + 4 * TILE, tid);   // Whh_r   (g0)
    cp_tile(sB1, img + 7 * TILE, tid);   // Wih_r   (g1)
    stage_A(agg, 128, M, node0, smem, tid);
    stage_A(h,   128, M, node0, smem + TILE, tid);

    float acc[2][8][4], rg[2][8][4], ng[2][8][4];

    // ---- P0: gh_r ----
    CP_WAIT(1);
    __syncthreads();
    zero_acc(acc);
    mma_pass(sAh, sB0, arow, akl, brow, bkl, acc);
    __syncthreads();
    cp_tile(sB0, img + 6 * TILE, tid);   // Whh_n   (g2)
    // ---- P1: + gi_r -> r ----
    CP_WAIT(1);
    __syncthreads();
    mma_pass(sA, sB1, arow, akl, brow, bkl, acc);
#pragma unroll
    for (int i = 0; i < 2; i++)
#pragma unroll
        for (int j = 0; j < 8; j++) {
            int c = cb + j * 8;
            float2 b1 = *reinterpret_cast<const float2*>(bih + c);
            float2 b2 = *reinterpret_cast<const float2*>(bhh + c);
#pragma unroll
            for (int rr = 0; rr < 2; rr++) {
                rg[i][j][rr * 2]     = sigm(acc[i][j][rr * 2]     + b1.x + b2.x);
                rg[i][j][rr * 2 + 1] = sigm(acc[i][j][rr * 2 + 1] + b1.y + b2.y);
            }
        }
    __syncthreads();
    cp_tile(sB1, img + 9 * TILE, tid);   // Wih_n   (g3)
    // ---- P2: gh_n ----
    CP_WAIT(1);
    __syncthreads();
    zero_acc(acc);
    mma_pass(sAh, sB0, arow, akl, brow, bkl, acc);
#pragma unroll
    for (int i = 0; i < 2; i++)
#pragma unroll
        for (int j = 0; j < 8; j++) {
            int c = cb + j * 8;
            float2 b1 = *reinterpret_cast<const float2*>(bih + 256 + c);
            float2 b2 = *reinterpret_cast<const float2*>(bhh + 256 + c);
#pragma unroll
            for (int rr = 0; rr < 2; rr++) {
                acc[i][j][rr * 2]     = rg[i][j][rr * 2]     * (acc[i][j][rr * 2]     + b2.x) + b1.x;
                acc[i][j][rr * 2 + 1] = rg[i][j][rr * 2 + 1] * (acc[i][j][rr * 2 + 1] + b2.y) + b1.y;
            }
        }
    __syncthreads();
    cp_tile(sB0, img + 5 * TILE, tid);   // Whh_z   (g4)
    // ---- P3: + gi_n -> n ----
    CP_WAIT(1);
    __syncthreads();
    mma_pass(sA, sB1, arow, akl, brow, bkl, acc);
#pragma unroll
    for (int i = 0; i < 2; i++)
#pragma unroll
        for (int j = 0; j < 8; j++)
#pragma unroll
            for (int q = 0; q < 4; q++) ng[i][j][q] = tanhf(acc[i][j][q]);
    __syncthreads();
    cp_tile(sB1, img + 8 * TILE, tid);   // Wih_z   (g5)
    // ---- P4: gh_z ----
    CP_WAIT(1);
    __syncthreads();
    zero_acc(acc);
    mma_pass(sAh, sB0, arow, akl, brow, bkl, acc);
    __syncthreads();
    if (mstep >= 0) cp_tile(sB0, img + (size_t)mstep * TILE, tid);   // W_m (g6)
    // ---- P5: + gi_z -> z ; combine; restage h_new into sA ----
    if (mstep >= 0) { CP_WAIT(1); } else { CP_WAIT(0); }
    __syncthreads();
    mma_pass(sA, sB1, arow, akl, brow, bkl, acc);
    __syncthreads();   // all warps done with A slots
#pragma unroll
    for (int i = 0; i < 2; i++)
#pragma unroll
        for (int rr = 0; rr < 2; rr++) {
            int rl = rl0 + i * 16 + rr * 8;
            int node = node0 + rl;
            bool valid = node < M;
#pragma unroll
            for (int j = 0; j < 8; j++) {
                int c = cb + j * 8;
                float2 b1 = *reinterpret_cast<const float2*>(bih + 128 + c);
                float2 b2 = *reinterpret_cast<const float2*>(bhh + 128 + c);
                float z0 = sigm(acc[i][j][rr * 2]     + b1.x + b2.x);
                float z1 = sigm(acc[i][j][rr * 2 + 1] + b1.y + b2.y);
                float2 hp = valid ? *reinterpret_cast<const float2*>(h + (size_t)node * 128 + c)
                                  : make_float2(0.f, 0.f);
                float h0 = (1.f - z0) * ng[i][j][rr * 2]     + z0 * hp.x;
                float h1 = (1.f - z1) * ng[i][j][rr * 2 + 1] + z1 * hp.y;
                if (valid)
                    *reinterpret_cast<float2*>(h + (size_t)node * 128 + c) = make_float2(h0, h1);
                __half2 hh = __floats2half2_rn(h0, h1);
                *reinterpret_cast<uint32_t*>(smem + swz(rl, c)) = *reinterpret_cast<uint32_t*>(&hh);
            }
        }

    // ---- P6: ym = fp16(h_new @ W[mstep]) ----
    if (mstep >= 0) {
        __syncthreads();
        CP_WAIT(0);
        zero_acc(acc);
        mma_pass(sA, sB0, arow, akl, brow, bkl, acc);
#pragma unroll
        for (int i = 0; i < 2; i++)
#pragma unroll
            for (int rr = 0; rr < 2; rr++) {
                int node = node0 + rl0 + i * 16 + rr * 8;
                if (node >= M) continue;
#pragma unroll
                for (int j = 0; j < 8; j++) {
                    int c = cb + j * 8;
                    __half2 h2 = __floats2half2_rn(acc[i][j][rr * 2], acc[i][j][rr * 2 + 1]);
                    *reinterpret_cast<uint32_t*>(ym + (size_t)node * 128 + c) =
                        *reinterpret_cast<uint32_t*>(&h2);
                }
            }
    }
}

// ---------------- pool: pool[b] += relu(h[n]), cnt[b] += 1 ------------------
__global__ void vspn_pool(const float* __restrict__ h, const int* __restrict__ batch,
                          float* __restrict__ pool, float* __restrict__ cnt, int Nn)
{
    __shared__ int sbh[128];
    int j  = threadIdx.x;
    int n0 = blockIdx.x * 128;
    int nend = min(n0 + 128, Nn);
    int cn = nend - n0;
    if (n0 + j < Nn) sbh[j] = batch[n0 + j];
    __syncthreads();
    float sum = 0.f, rc = 0.f;
    int cur = sbh[0];
    for (int t = 0; t < cn; t++) {
        int b = sbh[t];
        if (b != cur) {
            atomicAdd(&pool[(size_t)cur * HH + j], sum);
            if (j == 0) atomicAdd(&cnt[cur], rc);
            sum = 0.f; rc = 0.f; cur = b;
        }
        sum += fmaxf(h[(size_t)(n0 + t) * HH + j], 0.f);
        rc += 1.f;
    }
    atomicAdd(&pool[(size_t)cur * HH + j], sum);
    if (j == 0) atomicAdd(&cnt[cur], rc);
}

// ---------------- head ------------------------------------------------------
__global__ void vspn_head(const float* __restrict__ W1, const float* __restrict__ b1,
                          const float* __restrict__ W2, const float* __restrict__ b2,
                          float* __restrict__ out)
{
    int g = blockIdx.x;
    int k = threadIdx.x;
    __shared__ float gsh[256];
    __shared__ float tsh[256];
    float cb = fmaxf(d_cnt[g], 1.f);
    float cv = fmaxf(d_cnt[GG + g], 1.f);
    if (k < HH) gsh[k] = d_pool[(size_t)g * HH + k] / cb;
    else        gsh[k] = d_pool[(size_t)(GG + g) * HH + (k - HH)] / cv;
    __syncthreads();
    float acc = b1[k];
    for (int j = 0; j < 256; j++) acc += gsh[j] * W1[j * 256 + k];
    float t = fmaxf(acc, 0.f);
    tsh[k] = t * W2[k];
    __syncthreads();
    for (int s = 128; s > 0; s >>= 1) {
        if (k < s) tsh[k] += tsh[k + s];
        __syncthreads();
    }
    if (k == 0) {
        float x = tsh[0] + b2[0];
        out[g] = fmaxf(x, 0.f) + log1pf(expf(-fabsf(x)));
    }
}

// ---------------- launch ----------------------------------------------------
extern "C" void kernel_launch(void* const* d_in, const int* in_sizes, int n_in,
                              void* d_out, int out_size)
{
    const float* x_b   = (const float*)d_in[0];
    const int*   ei_b  = (const int*)  d_in[1];
    const int*   bat_b = (const int*)  d_in[2];
    const float* x_v   = (const float*)d_in[3];
    const int*   ei_v  = (const int*)  d_in[4];
    const int*   bat_v = (const int*)  d_in[5];
    const float* Wemb_b= (const float*)d_in[6];
    const float* Wemb_v= (const float*)d_in[7];
    const float* ggc   = (const float*)d_in[8];
    const float* w_ih  = (const float*)d_in[9];
    const float* w_hh  = (const float*)d_in[10];
    const float* b_ih  = (const float*)d_in[11];
    const float* b_hh  = (const float*)d_in[12];
    const float* W1    = (const float*)d_in[13];
    const float* b1    = (const float*)d_in[14];
    const float* W2    = (const float*)d_in[15];
    const float* b2    = (const float*)d_in[16];
    float* out = (float*)d_out;

    const int FB = in_sizes[0] / NN;
    const int FV = in_sizes[3] / NN;

    float *p_h, *p_agg, *p_pool, *p_cnt;
    __half* p_ym;
    char* p_img;
    int* p_ecnt;
    cudaGetSymbolAddress((void**)&p_h,    d_h);
    cudaGetSymbolAddress((void**)&p_ym,   d_ym);
    cudaGetSymbolAddress((void**)&p_agg,  d_agg);
    cudaGetSymbolAddress((void**)&p_img,  d_img);
    cudaGetSymbolAddress((void**)&p_pool, d_pool);
    cudaGetSymbolAddress((void**)&p_cnt,  d_cnt);
    cudaGetSymbolAddress((void**)&p_ecnt, d_ecnt);

    cudaFuncSetAttribute(vspn_emb,  cudaFuncAttributeMaxDynamicSharedMemorySize, SM_EMB);
    cudaFuncSetAttribute(vspn_step, cudaFuncAttributeMaxDynamicSharedMemorySize, SM_STEP);

    vspn_prep<<<(12 * 16384 + 255) / 256, 256>>>(ggc, w_ih, w_hh, Wemb_b, Wemb_v, FB, FV);
    cudaMemsetAsync(p_pool, 0, sizeof(float) * 2 * GG * HH);
    cudaMemsetAsync(p_cnt,  0, sizeof(float) * 2 * GG);

    const int MT = (NN + 127) / 128;                 // 782
    const int EB = (EE + 255) / 256;                 // 2344
    const int GB = (NN + 7) / 8;                     // gather: 8 warps/block
    const int poolBlocks = (NN + 127) / 128;

    for (int graph = 0; graph < 2; graph++) {
        const float* x   = graph ? x_v   : x_b;
        const int*   ei  = graph ? ei_v  : ei_b;
        const int*   bat = graph ? bat_v : bat_b;
        const int    F   = graph ? FV    : FB;

        // ---- CSR build for this graph ----
        cudaMemsetAsync(p_ecnt, 0, sizeof(int) * NN);
        k_hist<<<EB, 256>>>(ei);
        k_blocksum<<<NB_SCAN, 512>>>();
        k_scanbsum<<<1, 256>>>();
        k_scanfinal<<<NB_SCAN, 512>>>();
        k_fill<<<EB, 256>>>(ei);

        // ---- embed + m0 ----
        vspn_emb<<<MT, 256, SM_EMB>>>(x, F, p_img + (size_t)(10 + graph) * TILE,
                                      p_img, p_h, p_ym, NN);
        // ---- steps ----
        for (int s = 0; s < STEPS; s++) {
            vspn_gather<<<GB, 256>>>(p_ym, p_agg);
            int mstep = (s < STEPS - 1) ? (s + 1) : -1;
            vspn_step<<<MT, 256, SM_STEP>>>(p_agg, p_h, p_img, mstep,
                                            b_ih, b_hh, p_ym, NN);
        }
        vspn_pool<<<poolBlocks, 128>>>(p_h, bat,
                                       p_pool + (size_t)graph * GG * HH,
                                       p_cnt + graph * GG, NN);
    }

    vspn_head<<<GG, 256>>>(W1, b1, W2, b2, out);
}